// round 7
// baseline (speedup 1.0000x reference)
#include <cuda_runtime.h>
#include <math.h>

// Problem constants (fixed by setup_inputs)
#define NN 100000
#define EE 1600000
#define HH 4
#define CC 16
#define DD 64
#define FF 128
#define ET_MAX (EE + NN)
#define NODES_PER_BLK 1024
#define MAX_SCAN_BLKS 128

// ---------------- scratch (device globals; no runtime allocation) ----------------
// INVARIANTS at kernel_launch entry (zero-init at load; restored every call):
//   g_deg  all-zero  (scan_lookback re-zeroes after consuming)
//   g_flag all-zero  (scatter8 re-zeroes after scan completes)
// g_csr_src holds BYTE offsets (node*256) and has a 16-entry safety pad (zeros).
__device__ float g_xl[(size_t)NN * DD];
__device__ float g_xr[(size_t)NN * DD];
__device__ float g_h1[(size_t)NN * DD];
__device__ int   g_deg[NN];
__device__ int   g_off[NN + 1];
__device__ int   g_cur[NN];
__device__ unsigned g_flag[MAX_SCAN_BLKS];
__device__ int   g_csr_src[ET_MAX + 16];

// ---------------- helpers ----------------
__device__ __forceinline__ void ffma2(unsigned long long& acc,
                                      unsigned long long a, unsigned long long b) {
    asm("fma.rn.f32x2 %0, %1, %2, %0;" : "+l"(acc) : "l"(a), "l"(b));
}
__device__ __forceinline__ unsigned long long add2(unsigned long long a,
                                                   unsigned long long b) {
    unsigned long long r;
    asm("add.rn.f32x2 %0, %1, %2;" : "=l"(r) : "l"(a), "l"(b));
    return r;
}
__device__ __forceinline__ unsigned long long bcast2(float v) {
    unsigned long long r;
    asm("mov.b64 %0, {%1, %1};" : "=l"(r) : "r"(__float_as_uint(v)));
    return r;
}
__device__ __forceinline__ unsigned long long pack2(float lo, float hi) {
    unsigned long long r;
    asm("mov.b64 %0, {%1, %2};" : "=l"(r) : "r"(__float_as_uint(lo)), "r"(__float_as_uint(hi)));
    return r;
}
__device__ __forceinline__ float2 unpack2(unsigned long long v) {
    unsigned int lo, hi;
    asm("mov.b64 {%0, %1}, %2;" : "=r"(lo), "=r"(hi) : "l"(v));
    return make_float2(__uint_as_float(lo), __uint_as_float(hi));
}
#define ABS2_MASK 0x7FFFFFFF7FFFFFFFULL

// ================= GEMM body: 128 rows x (Wl||Wr 64+64 cols), 8x8 per thread =================
template<int K>
__device__ __forceinline__ void gemm_body(int blk,
                                          const float* __restrict__ X,
                                          const float* __restrict__ Wl,
                                          const float* __restrict__ Wr,
                                          float* __restrict__ xl,
                                          float* __restrict__ xr, int n,
                                          float (*As)[132], float (*Bs)[132]) {
    int tid = threadIdx.x;
    int rg = tid >> 4;
    int cg = tid & 15;
    int row0 = blk * 128;

    unsigned long long cl[8][2], cr[8][2];
#pragma unroll
    for (int i = 0; i < 8; i++) { cl[i][0] = cl[i][1] = cr[i][0] = cr[i][1] = 0ULL; }

    int lr  = tid >> 1;
    int lks = (tid & 1) * 8;
    int bk  = tid >> 4;
    int bc  = (tid & 15) * 8;

    for (int kc = 0; kc < K; kc += 16) {
        {
            int grow = row0 + lr;
            float4 v0 = make_float4(0.f, 0.f, 0.f, 0.f), v1 = v0;
            if (grow < n) {
                const float* g = X + (size_t)grow * K + kc + lks;
                v0 = *(const float4*)g;
                v1 = *(const float4*)(g + 4);
            }
            As[lks + 0][lr] = v0.x; As[lks + 1][lr] = v0.y;
            As[lks + 2][lr] = v0.z; As[lks + 3][lr] = v0.w;
            As[lks + 4][lr] = v1.x; As[lks + 5][lr] = v1.y;
            As[lks + 6][lr] = v1.z; As[lks + 7][lr] = v1.w;
        }
        {
            const float* wsrc = (bc < 64) ? (Wl + (size_t)(kc + bk) * DD + bc)
                                          : (Wr + (size_t)(kc + bk) * DD + (bc - 64));
            *(float4*)&Bs[bk][bc]     = *(const float4*)wsrc;
            *(float4*)&Bs[bk][bc + 4] = *(const float4*)(wsrc + 4);
        }
        __syncthreads();

#pragma unroll
        for (int k = 0; k < 16; k++) {
            float4 a01 = *(const float4*)&As[k][rg * 8];
            float4 a23 = *(const float4*)&As[k][rg * 8 + 4];
            ulonglong2 bl = *(const ulonglong2*)&Bs[k][cg * 4];
            ulonglong2 br = *(const ulonglong2*)&Bs[k][cg * 4 + 64];
            unsigned long long ab[8];
            ab[0] = bcast2(a01.x); ab[1] = bcast2(a01.y);
            ab[2] = bcast2(a01.z); ab[3] = bcast2(a01.w);
            ab[4] = bcast2(a23.x); ab[5] = bcast2(a23.y);
            ab[6] = bcast2(a23.z); ab[7] = bcast2(a23.w);
#pragma unroll
            for (int i = 0; i < 8; i++) {
                ffma2(cl[i][0], ab[i], bl.x); ffma2(cl[i][1], ab[i], bl.y);
                ffma2(cr[i][0], ab[i], br.x); ffma2(cr[i][1], ab[i], br.y);
            }
        }
        __syncthreads();
    }

#pragma unroll
    for (int i = 0; i < 8; i++) {
        int row = row0 + rg * 8 + i;
        if (row < n) {
            *(ulonglong2*)(xl + (size_t)row * DD + cg * 4) = make_ulonglong2(cl[i][0], cl[i][1]);
            *(ulonglong2*)(xr + (size_t)row * DD + cg * 4) = make_ulonglong2(cr[i][0], cr[i][1]);
        }
    }
}

// ---------------- hist body: 8 edges per thread ----------------
__device__ __forceinline__ void hist_body(int blk, const int* __restrict__ dst, int E) {
    int i = (blk * 256 + threadIdx.x) * 8;
    if (i + 7 < E) {
        int4 a = *(const int4*)(dst + i);
        int4 b = *(const int4*)(dst + i + 4);
        atomicAdd(&g_deg[a.x], 1); atomicAdd(&g_deg[a.y], 1);
        atomicAdd(&g_deg[a.z], 1); atomicAdd(&g_deg[a.w], 1);
        atomicAdd(&g_deg[b.x], 1); atomicAdd(&g_deg[b.y], 1);
        atomicAdd(&g_deg[b.z], 1); atomicAdd(&g_deg[b.w], 1);
    } else {
        for (int j = 0; j < 8; j++)
            if (i + j < E) atomicAdd(&g_deg[__ldg(dst + i + j)], 1);
    }
}

// ================= fat kernel 1: gemm1 (even blocks) + hist (odd blocks) =================
__global__ __launch_bounds__(256, 2)
void fat_gemm1_hist(const float* __restrict__ X,
                    const float* __restrict__ Wl,
                    const float* __restrict__ Wr,
                    float* __restrict__ xl, float* __restrict__ xr, int n,
                    const int* __restrict__ dst, int E, int gGemm, int gHist) {
    __shared__ float As[16][132];
    __shared__ float Bs[16][132];
    int bid = blockIdx.x;
    int g = bid >> 1;
    if ((bid & 1) == 0) {
        if (g < gGemm) gemm_body<FF>(g, X, Wl, Wr, xl, xr, n, As, Bs);
    } else {
        if (g < gHist) hist_body(g, dst, E);
    }
}

// ================= standalone GEMM (layer 2) =================
template<int K>
__global__ __launch_bounds__(256, 2)
void gemm_tiled(const float* __restrict__ X,
                const float* __restrict__ Wl,
                const float* __restrict__ Wr,
                float* __restrict__ xl, float* __restrict__ xr, int n) {
    __shared__ float As[16][132];
    __shared__ float Bs[16][132];
    gemm_body<K>(blockIdx.x, X, Wl, Wr, xl, xr, n, As, Bs);
}

// ================= decoupled-lookback scan (one kernel) =================
__global__ void scan_lookback(int n, int nblk) {
    __shared__ int sh[256];
    __shared__ int s_prefix;
    int t = threadIdx.x, b = blockIdx.x;
    int i0 = b * NODES_PER_BLK + t * 4;

    int d0 = 0, d1 = 0, d2 = 0, d3 = 0;
    if (i0 + 3 < n) {
        int4 d = *(const int4*)(g_deg + i0);
        d0 = d.x + 1; d1 = d.y + 1; d2 = d.z + 1; d3 = d.w + 1;
        *(int4*)(g_deg + i0) = make_int4(0, 0, 0, 0);
    } else {
        if (i0 + 0 < n) { d0 = g_deg[i0 + 0] + 1; g_deg[i0 + 0] = 0; }
        if (i0 + 1 < n) { d1 = g_deg[i0 + 1] + 1; g_deg[i0 + 1] = 0; }
        if (i0 + 2 < n) { d2 = g_deg[i0 + 2] + 1; g_deg[i0 + 2] = 0; }
        if (i0 + 3 < n) { d3 = g_deg[i0 + 3] + 1; g_deg[i0 + 3] = 0; }
    }
    int tsum = d0 + d1 + d2 + d3;
    sh[t] = tsum; __syncthreads();
    for (int d = 1; d < 256; d <<= 1) {
        int v = (t >= d) ? sh[t - d] : 0;
        __syncthreads();
        sh[t] += v;
        __syncthreads();
    }
    int T = sh[255];

    volatile unsigned* flag = g_flag;
    if (t == 0) {
        if (b == 0) {
            s_prefix = 0;
            flag[0] = (2u << 30) | (unsigned)T;
        } else {
            flag[b] = (1u << 30) | (unsigned)T;
            unsigned run = 0;
            int j = b - 1;
            while (true) {
                unsigned v = flag[j];
                unsigned st = v >> 30;
                if (st == 0) continue;
                run += v & 0x3FFFFFFFu;
                if (st == 2u) break;
                j--;
            }
            s_prefix = (int)run;
            flag[b] = (2u << 30) | (run + (unsigned)T);
        }
    }
    __syncthreads();
    int base = s_prefix + sh[t] - tsum;

    int dd[4] = {d0, d1, d2, d3};
    int o = base;
    for (int j = 0; j < 4; j++) {
        int i = i0 + j;
        if (i < n) {
            g_off[i] = o;
            g_csr_src[o] = i << 8;     // self loop first (BYTE offset: node*256)
            g_cur[i] = o + 1;
        }
        o += dd[j];
    }
    if (b == nblk - 1 && t == 255) g_off[n] = s_prefix + T;
}

// ================= scatter (stores BYTE offsets; restores g_flag) =================
__global__ void scatter8(const int* __restrict__ src,
                         const int* __restrict__ dst, int E) {
    if (blockIdx.x == 0 && threadIdx.x < MAX_SCAN_BLKS)
        g_flag[threadIdx.x] = 0;
    int i = (blockIdx.x * blockDim.x + threadIdx.x) * 8;
    if (i + 7 < E) {
        int4 sa = *(const int4*)(src + i);
        int4 da = *(const int4*)(dst + i);
        int4 sb = *(const int4*)(src + i + 4);
        int4 db = *(const int4*)(dst + i + 4);
        int p0 = atomicAdd(&g_cur[da.x], 1);
        int p1 = atomicAdd(&g_cur[da.y], 1);
        int p2 = atomicAdd(&g_cur[da.z], 1);
        int p3 = atomicAdd(&g_cur[da.w], 1);
        int p4 = atomicAdd(&g_cur[db.x], 1);
        int p5 = atomicAdd(&g_cur[db.y], 1);
        int p6 = atomicAdd(&g_cur[db.z], 1);
        int p7 = atomicAdd(&g_cur[db.w], 1);
        g_csr_src[p0] = sa.x << 8; g_csr_src[p1] = sa.y << 8;
        g_csr_src[p2] = sa.z << 8; g_csr_src[p3] = sa.w << 8;
        g_csr_src[p4] = sb.x << 8; g_csr_src[p5] = sb.y << 8;
        g_csr_src[p6] = sb.z << 8; g_csr_src[p7] = sb.w << 8;
    } else {
        for (int j = 0; j < 8; j++)
            if (i + j < E) {
                int s = __ldg(src + i + j), d = __ldg(dst + i + j);
                g_csr_src[atomicAdd(&g_cur[d], 1)] = s << 8;
            }
    }
}

// ================= fused GATv2 attention + aggregate + bias + ReLU =================
// warp per dst node; 16 lanes/edge (lane owns 4 dims), 2 edges per step.
// CSR entries are byte offsets; no index clamping (16-entry pad; p=0 discards
// out-of-segment contributions). Score uses lrelu(u)=0.6u+0.4|u| with
// pre-scaled att and packed f32x2 math.
__global__ void gat_node(const float* __restrict__ xl,
                         const float* __restrict__ xr,
                         const float* __restrict__ att,
                         const float* __restrict__ bias,
                         float* __restrict__ out, int n) {
    int w    = (blockIdx.x * blockDim.x + threadIdx.x) >> 5;
    int lane = threadIdx.x & 31;
    if (w >= n) return;
    int half = lane >> 4;
    int sub  = lane & 15;

    const char* xlb = (const char*)xl + sub * 16;   // per-lane base
    float4 xrv  = *(const float4*)(xr  + (size_t)w * DD + sub * 4);
    float4 attv = *(const float4*)(att + sub * 4);

    unsigned long long xr01 = pack2(xrv.x, xrv.y), xr23 = pack2(xrv.z, xrv.w);
    unsigned long long a06_01 = pack2(0.6f * attv.x, 0.6f * attv.y);
    unsigned long long a06_23 = pack2(0.6f * attv.z, 0.6f * attv.w);
    unsigned long long a04_01 = pack2(0.4f * attv.x, 0.4f * attv.y);
    unsigned long long a04_23 = pack2(0.4f * attv.z, 0.4f * attv.w);

    int beg = g_off[w], end = g_off[w + 1];
    int rem = end - beg;
    const int* ip = g_csr_src + beg;

    float s = 0.f;
    unsigned long long acc01 = 0ULL, acc23 = 0ULL;

    // pipeline prologue: rows for trip 0, offsets for trip 1
    int c0 = __ldg(ip + half);
    int c1 = __ldg(ip + 2 + half);
    ulonglong2 v0 = *(const ulonglong2*)(xlb + c0);
    ulonglong2 v1 = *(const ulonglong2*)(xlb + c1);
    int n0 = __ldg(ip + 4 + half);
    int n1 = __ldg(ip + 6 + half);

    for (int i = 0; i < rem; i += 4) {
        // prefetch: rows for trip i+4, offsets for trip i+8
        ulonglong2 w0 = *(const ulonglong2*)(xlb + n0);
        ulonglong2 w1 = *(const ulonglong2*)(xlb + n1);
        int m0 = __ldg(ip + i + 8 + half);
        int m1 = __ldg(ip + i + 10 + half);

        unsigned long long u01 = add2(v0.x, xr01), u23 = add2(v0.y, xr23);
        unsigned long long t2 = 0ULL;
        ffma2(t2, a06_01, u01); ffma2(t2, a04_01, u01 & ABS2_MASK);
        ffma2(t2, a06_23, u23); ffma2(t2, a04_23, u23 & ABS2_MASK);
        float2 tp = unpack2(t2);
        float t0 = tp.x + tp.y;

        u01 = add2(v1.x, xr01); u23 = add2(v1.y, xr23);
        t2 = 0ULL;
        ffma2(t2, a06_01, u01); ffma2(t2, a04_01, u01 & ABS2_MASK);
        ffma2(t2, a06_23, u23); ffma2(t2, a04_23, u23 & ABS2_MASK);
        tp = unpack2(t2);
        float t1 = tp.x + tp.y;

        t0 += __shfl_xor_sync(0xffffffffu, t0, 1);
        t1 += __shfl_xor_sync(0xffffffffu, t1, 1);
        t0 += __shfl_xor_sync(0xffffffffu, t0, 2);
        t1 += __shfl_xor_sync(0xffffffffu, t1, 2);

        float p0 = (i + half     < rem) ? __expf(t0) : 0.f;
        float p1 = (i + 2 + half < rem) ? __expf(t1) : 0.f;
        s += p0 + p1;
        unsigned long long pp0 = bcast2(p0), pp1 = bcast2(p1);
        ffma2(acc01, pp0, v0.x); ffma2(acc23, pp0, v0.y);
        ffma2(acc01, pp1, v1.x); ffma2(acc23, pp1, v1.y);

        v0 = w0; v1 = w1; n0 = m0; n1 = m1;
    }

    float2 f01 = unpack2(acc01), f23 = unpack2(acc23);
    float a0 = f01.x, a1 = f01.y, a2 = f23.x, a3 = f23.y;

    // combine the two half-warps (disjoint edge sets, same dims)
    s  += __shfl_xor_sync(0xffffffffu, s,  16);
    a0 += __shfl_xor_sync(0xffffffffu, a0, 16);
    a1 += __shfl_xor_sync(0xffffffffu, a1, 16);
    a2 += __shfl_xor_sync(0xffffffffu, a2, 16);
    a3 += __shfl_xor_sync(0xffffffffu, a3, 16);

    if (half == 0) {
        float4 bv = *(const float4*)(bias + sub * 4);
        float inv = __fdividef(1.f, s);
        float4 o;
        o.x = fmaxf(fmaf(a0, inv, bv.x), 0.f);
        o.y = fmaxf(fmaf(a1, inv, bv.y), 0.f);
        o.z = fmaxf(fmaf(a2, inv, bv.z), 0.f);
        o.w = fmaxf(fmaf(a3, inv, bv.w), 0.f);
        *(float4*)(out + (size_t)w * DD + sub * 4) = o;
    }
}

// ---------------- launch ----------------
extern "C" void kernel_launch(void* const* d_in, const int* in_sizes, int n_in,
                              void* d_out, int out_size) {
    const float* x    = (const float*)d_in[0];
    const int*   edge = (const int*)  d_in[1];
    const float* W1l  = (const float*)d_in[2];
    const float* W1r  = (const float*)d_in[3];
    const float* att1 = (const float*)d_in[4];
    const float* b1   = (const float*)d_in[5];
    const float* W2l  = (const float*)d_in[6];
    const float* W2r  = (const float*)d_in[7];
    const float* att2 = (const float*)d_in[8];
    const float* b2   = (const float*)d_in[9];

    int E = in_sizes[1] / 2;
    int N = in_sizes[0] / FF;
    const int* srcp = edge;
    const int* dstp = edge + E;
    float* out = (float*)d_out;

    float *xl, *xr, *h1;
    cudaGetSymbolAddress((void**)&xl, g_xl);
    cudaGetSymbolAddress((void**)&xr, g_xr);
    cudaGetSymbolAddress((void**)&h1, g_h1);

    const int TB = 256;
    int gGemm = (N + 127) / 128;
    int gHist = (E + TB * 8 - 1) / (TB * 8);
    int gFat  = 2 * (gGemm > gHist ? gGemm : gHist);
    int nblk  = (N + NODES_PER_BLK - 1) / NODES_PER_BLK;
    int gNode = (N * 32 + TB - 1) / TB;

    // 1: gemm1 + degree histogram (interleaved by block parity)
    fat_gemm1_hist<<<gFat, TB>>>(x, W1l, W1r, xl, xr, N, dstp, E, gGemm, gHist);
    // 2: CSR offsets via decoupled lookback (restores g_deg)
    scan_lookback<<<nblk, TB>>>(N, nblk);
    // 3: CSR scatter (byte offsets; restores g_flag)
    scatter8<<<(E + TB * 8 - 1) / (TB * 8), TB>>>(srcp, dstp, E);
    // 4: layer-1 attention (profiled slot)
    gat_node<<<gNode, TB>>>(xl, xr, att1, b1, h1, N);
    // 5: layer-2 GEMM
    gemm_tiled<DD><<<gGemm, TB>>>(h1, W2l, W2r, xl, xr, N);
    // 6: layer-2 attention
    gat_node<<<gNode, TB>>>(xl, xr, att2, b2, out, N);
}